// round 2
// baseline (speedup 1.0000x reference)
#include <cuda_runtime.h>
#include <math.h>

#define TT 10000
#define BB 4096
#define NTH 1024
#define PER 10          // ceil(TT / NTH)
#define TCHUNK 32
#define DEPS 1e-12

// fp32-rounded constants (match np.float32 of the reference constants)
#define LOG_GAMMA_F  (0.019802627296179712f)
#define ALPHA_F      (-1.0050335853501441e-05f)
#define INIT_LOGW_F  (-1.3943265328171549f)
#define INIT_LOGP_F  (-6.907755278982137f)

// Scratch (device globals — no allocation allowed)
__device__ float  d_thr[TT];
__device__ float  d_filt[TT];
__device__ double d_S[TT + 1];
__device__ int    d_death[BB];
__device__ int    d_Tcut;

__device__ __forceinline__ double block_exscan(double v, double* sbuf, int tid,
                                               double* total) {
    sbuf[tid] = v;
    __syncthreads();
    #pragma unroll 1
    for (int off = 1; off < NTH; off <<= 1) {
        double x = (tid >= off) ? sbuf[tid - off] : 0.0;
        __syncthreads();
        sbuf[tid] += x;
        __syncthreads();
    }
    double ex = (tid == 0) ? 0.0 : sbuf[tid - 1];
    *total = sbuf[NTH - 1];
    __syncthreads();
    return ex;
}

// ---------------------------------------------------------------------------
// Kernel 1: batch-independent precompute.
//   logw_t, logp_t via block prefix scans; thr[t] = exp(logit_t) - eps;
//   filt[t] = conservative u2 lower bound for any death at step t;
//   S[k] = sum_{t<k} exp(logw_{t+1}/1000);  T_cut = first t with thr <= 0.
// Also resets per-launch scratch (graph replays reuse globals).
// __launch_bounds__(NTH) caps regs at 64 so 1024-thread launch fits; the
// resulting local spills are negligible for this one-block kernel.
// ---------------------------------------------------------------------------
__global__ void __launch_bounds__(NTH) setup_kernel(const float* __restrict__ acts) {
    __shared__ double sbuf[NTH];
    int tid = threadIdx.x;

    for (int i = tid; i < BB; i += NTH) d_death[i] = TT;
    if (tid == 0) d_Tcut = TT;
    // ordering of resets vs later atomics is provided by the scan syncthreads

    int base = tid * PER;

    // Pass A: c_t = LOG_GAMMA + log(1 - exp(a_t));  logw_t = INIT_LOGW + prefix(c)
    double cc[PER], lwex[PER];
    double run = 0.0;
    #pragma unroll
    for (int j = 0; j < PER; j++) {
        int t = base + j;
        double c = 0.0;
        if (t < TT) {
            float f = expf(acts[t]);
            c = (double)LOG_GAMMA_F + (double)logf(1.0f - f);
        }
        lwex[j] = run;
        run += c;
        cc[j] = c;
    }
    double totA;
    double exA = block_exscan(run, sbuf, tid, &totA);

    // Pass B: g_t = ALPHA * exp(a_t) * exp(logw_t);  logp_t = INIT_LOGP + prefix(g)
    double gex[PER];
    run = 0.0;
    #pragma unroll
    for (int j = 0; j < PER; j++) {
        int t = base + j;
        double g = 0.0;
        if (t < TT) {
            double lw = (double)INIT_LOGW_F + exA + lwex[j];
            double f  = (double)expf(acts[t]);
            g = (double)ALPHA_F * f * exp(lw);
        }
        gex[j] = run;
        run += g;
    }
    double totB;
    double exB = block_exscan(run, sbuf, tid, &totB);

    #pragma unroll
    for (int j = 0; j < PER; j++) {
        int t = base + j;
        if (t < TT) {
            double logp  = (double)INIT_LOGP_F + exB + gex[j];
            double elp   = exp(logp);
            double logit = logp - log1p(-elp);
            double thr   = exp(logit) - DEPS;
            if (!(thr > 0.0)) {
                // death impossible at/after here: noise <= -log(eps) = 27.631
                d_thr[t]  = 0.0f;
                d_filt[t] = 2.0f;   // never passes
                atomicMin(&d_Tcut, t);
            } else {
                d_thr[t] = (float)thr;
                // necessary condition for death: u2 + eps > exp(-27.631*thr)
                // use -27.632 and -1e-4 absolute margin (conservative)
                double flt = exp(-27.632 * thr) - DEPS - 1e-4;
                d_filt[t] = (float)flt;
            }
        }
    }

    // Pass C: rwd_t = exp(logw_{t+1} / 1000);  S[k] = prefix(rwd)
    double rex[PER];
    run = 0.0;
    #pragma unroll
    for (int j = 0; j < PER; j++) {
        int t = base + j;
        double r = 0.0;
        if (t < TT) {
            double lwpost = (double)INIT_LOGW_F + exA + lwex[j] + cc[j];
            r = exp(lwpost / 1000.0);
        }
        rex[j] = run;
        run += r;
    }
    double totC;
    double exC = block_exscan(run, sbuf, tid, &totC);
    #pragma unroll
    for (int j = 0; j < PER; j++) {
        int t = base + j;
        if (t < TT) d_S[t] = exC + rex[j];
    }
    if (tid == 0) d_S[TT] = totC;
}

// ---------------------------------------------------------------------------
// Kernel 2: streaming death-scan over t < T_cut.
//   death at (t,b)  <=>  log(u2+eps) > thr_t * log(u1+eps)
//   Filter on u2 first so logs (MUFU) run on only ~3% of samples and u1 is
//   loaded only when needed.
// ---------------------------------------------------------------------------
__global__ void __launch_bounds__(256) scan_kernel(const float* __restrict__ u1,
                                                   const float* __restrict__ u2) {
    int b    = blockIdx.x * blockDim.x + threadIdx.x;
    int t0   = blockIdx.y * TCHUNK;
    int tcut = d_Tcut;
    if (t0 >= tcut) return;
    int tend = min(t0 + TCHUNK, tcut);

    int myd = TT;
    #pragma unroll 1
    for (int t = t0; t < tend; t += 8) {
        float v[8];
        #pragma unroll
        for (int j = 0; j < 8; j++) {
            int tt = t + j;
            v[j] = (tt < tend) ? __ldcs(&u2[(size_t)tt * BB + b]) : 0.0f;
        }
        #pragma unroll
        for (int j = 0; j < 8; j++) {
            int tt = t + j;
            if (tt < tend && v[j] > d_filt[tt]) {
                float u1v = __ldcs(&u1[(size_t)tt * BB + b]);
                float L1  = logf(u1v + 1e-12f);
                float L2  = logf(v[j] + 1e-12f);
                if (L2 > d_thr[tt] * L1 && tt < myd) myd = tt;
            }
        }
    }
    if (myd < TT) atomicMin(&d_death[b], myd);
}

// ---------------------------------------------------------------------------
// Kernel 3: cumrew_b = S[death_b]; mean over batch.
// ---------------------------------------------------------------------------
__global__ void __launch_bounds__(NTH) finalize_kernel(float* __restrict__ out) {
    __shared__ double red[NTH];
    int tid = threadIdx.x;
    double s = 0.0;
    for (int b = tid; b < BB; b += NTH) {
        int d = d_death[b];           // in [0, TT]
        s += d_S[d];
    }
    red[tid] = s;
    __syncthreads();
    #pragma unroll 1
    for (int off = NTH / 2; off > 0; off >>= 1) {
        if (tid < off) red[tid] += red[tid + off];
        __syncthreads();
    }
    if (tid == 0) out[0] = (float)(red[0] / (double)BB);
}

extern "C" void kernel_launch(void* const* d_in, const int* in_sizes, int n_in,
                              void* d_out, int out_size) {
    const float* acts = (const float*)d_in[0];
    const float* u1   = (const float*)d_in[1];
    const float* u2   = (const float*)d_in[2];
    float* out = (float*)d_out;

    setup_kernel<<<1, NTH>>>(acts);
    dim3 grid(BB / 256, (TT + TCHUNK - 1) / TCHUNK);
    scan_kernel<<<grid, 256>>>(u1, u2);
    finalize_kernel<<<1, NTH>>>(out);
}

// round 3
// speedup vs baseline: 4.1577x; 4.1577x over previous
#include <cuda_runtime.h>
#include <math.h>

#define TT 10000
#define BB 4096
#define NTH 1024
#define PER 10          // ceil(TT / NTH)
#define TCHUNK 32
#define SCAN_THREADS 256

// fp32-rounded constants (match np.float32 of the reference constants)
#define LOG_GAMMA_F  (0.019802627296179712f)
#define ALPHA_F      (-1.0050335853501441e-05f)
#define INIT_LOGW_F  (-1.3943265328171549f)
#define INIT_LOGP_F  (-6.907755278982137f)

// Scratch (device globals — no allocation allowed)
__device__ float  d_thr[TT];
__device__ float  d_filt[TT];
__device__ float  d_c[TT];      // c_t  = LOG_GAMMA + log1p(-exp(a_t))
__device__ float  d_lw[TT];     // logw_pre[t]
__device__ double d_S[TT + 1];
__device__ int    d_death[BB];
__device__ int    d_Tcut;

__device__ __forceinline__ double block_exscan(double v, double* sbuf, int tid) {
    sbuf[tid] = v;
    __syncthreads();
    #pragma unroll 1
    for (int off = 1; off < NTH; off <<= 1) {
        double x = (tid >= off) ? sbuf[tid - off] : 0.0;
        __syncthreads();
        sbuf[tid] += x;
        __syncthreads();
    }
    double ex = (tid == 0) ? 0.0 : sbuf[tid - 1];
    __syncthreads();
    return ex;
}

// ---------------------------------------------------------------------------
// Kernel 1: batch-independent precompute. All per-element transcendentals in
// FLOAT (MUFU); only cross-element accumulation in double (DADD only).
// No per-thread register arrays — intermediates staged via global scratch
// between barrier-separated phases (barriers order global writes in-block).
// ---------------------------------------------------------------------------
__global__ void __launch_bounds__(NTH) setup_kernel(const float* __restrict__ acts) {
    __shared__ double sbuf[NTH];
    int tid = threadIdx.x;
    int base = tid * PER;

    // reset per-launch scratch (graph replays reuse globals)
    for (int i = tid; i < BB; i += NTH) d_death[i] = TT;
    if (tid == 0) d_Tcut = TT;
    // (barriers inside the first exscan order these vs later atomics)

    // ---- Phase A: c_t; chunk sums; exscan; write logw_pre[t] ----
    double run = 0.0;
    #pragma unroll
    for (int j = 0; j < PER; j++) {
        int t = base + j;
        if (t < TT) {
            float f = expf(acts[t]);
            float c = LOG_GAMMA_F + log1pf(-f);
            d_c[t] = c;
            run += (double)c;
        }
    }
    double exA = block_exscan(run, sbuf, tid);
    run = exA;
    #pragma unroll
    for (int j = 0; j < PER; j++) {
        int t = base + j;
        if (t < TT) {
            d_lw[t] = (float)((double)INIT_LOGW_F + run);
            run += (double)d_c[t];
        }
    }
    __syncthreads();

    // ---- Phase B: g_t = ALPHA * f_t * exp(logw_pre[t]); logp_pre prefix;
    //      thr[t], filt[t], T_cut ----
    run = 0.0;
    #pragma unroll
    for (int j = 0; j < PER; j++) {
        int t = base + j;
        if (t < TT) {
            float f = expf(acts[t]);
            float g = ALPHA_F * f * expf(d_lw[t]);   // -> -inf after logw>88: ok
            run += (double)g;
        }
    }
    double exB = block_exscan(run, sbuf, tid);
    run = exB;
    #pragma unroll
    for (int j = 0; j < PER; j++) {
        int t = base + j;
        if (t < TT) {
            float logp = (float)((double)INIT_LOGP_F + run);
            float f = expf(acts[t]);
            run += (double)(ALPHA_F * f * expf(d_lw[t]));
            float elp   = expf(logp);
            float logit = logp - log1pf(-elp);
            float thr   = expf(logit) - 1e-12f;
            if (!(thr > 0.0f)) {
                // death impossible at/after here: noise <= -log(eps) = 27.631
                d_thr[t]  = 0.0f;
                d_filt[t] = 2.0f;   // never passes
                atomicMin(&d_Tcut, t);
            } else {
                d_thr[t] = thr;
                // necessary condition for death: u2 + eps > exp(-27.631*thr)
                // conservative: -27.632 slope and -1e-4 absolute margin
                d_filt[t] = expf(-27.632f * thr) - 1e-12f - 1e-4f;
            }
        }
    }

    // ---- Phase C: rwd_t = exp(logw_post[t]/1000); S[k] = prefix(rwd) ----
    run = 0.0;
    #pragma unroll
    for (int j = 0; j < PER; j++) {
        int t = base + j;
        if (t < TT) {
            float lwpost = d_lw[t] + d_c[t];
            run += (double)expf(lwpost * 0.001f);
        }
    }
    double exC = block_exscan(run, sbuf, tid);
    run = exC;
    #pragma unroll
    for (int j = 0; j < PER; j++) {
        int t = base + j;
        if (t < TT) {
            d_S[t] = run;
            float lwpost = d_lw[t] + d_c[t];
            run += (double)expf(lwpost * 0.001f);
        }
    }
    if (base + PER >= TT && base < TT) d_S[TT] = run;  // last active thread
}

// ---------------------------------------------------------------------------
// Kernel 2: streaming death-scan over t < T_cut.
//   death at (t,b)  <=>  log(u2+eps) > thr_t * log(u1+eps)
//   float4 u2 loads; u2 pre-filter keeps logs (MUFU) + u1 loads to ~3%.
// ---------------------------------------------------------------------------
__global__ void __launch_bounds__(SCAN_THREADS) scan_kernel(
        const float* __restrict__ u1, const float* __restrict__ u2) {
    __shared__ float s_thr[TCHUNK];
    __shared__ float s_filt[TCHUNK];

    int tcut = d_Tcut;
    int t0   = blockIdx.y * TCHUNK;
    if (t0 >= tcut) return;
    int nt = min(TCHUNK, tcut - t0);

    if (threadIdx.x < TCHUNK) {
        int tt = t0 + threadIdx.x;
        bool ok = (threadIdx.x < nt);
        s_thr [threadIdx.x] = ok ? d_thr [tt] : 0.0f;
        s_filt[threadIdx.x] = ok ? d_filt[tt] : 2.0f;
    }
    __syncthreads();

    int b4 = (blockIdx.x * SCAN_THREADS + threadIdx.x) * 4;
    const float4* u2v = (const float4*)u2;

    #pragma unroll 1
    for (int t = 0; t < nt; t += 4) {
        float4 v[4];
        #pragma unroll
        for (int j = 0; j < 4; j++) {
            int tt = t + j;
            v[j] = (tt < nt) ? __ldcs(&u2v[((size_t)(t0 + tt) * BB + b4) >> 2])
                             : make_float4(0.f, 0.f, 0.f, 0.f);
        }
        #pragma unroll
        for (int j = 0; j < 4; j++) {
            int tt = t + j;
            if (tt >= nt) break;
            float flt = s_filt[tt];
            float th  = s_thr[tt];
            int   tg  = t0 + tt;
            float lane[4] = {v[j].x, v[j].y, v[j].z, v[j].w};
            #pragma unroll
            for (int l = 0; l < 4; l++) {
                if (lane[l] > flt) {
                    float u1v = __ldcs(&u1[(size_t)tg * BB + b4 + l]);
                    float L1  = logf(u1v + 1e-12f);
                    float L2  = logf(lane[l] + 1e-12f);
                    if (L2 > th * L1) atomicMin(&d_death[b4 + l], tg);
                }
            }
        }
    }
}

// ---------------------------------------------------------------------------
// Kernel 3: cumrew_b = S[death_b]; mean over batch.
// ---------------------------------------------------------------------------
__global__ void __launch_bounds__(NTH) finalize_kernel(float* __restrict__ out) {
    __shared__ double red[NTH];
    int tid = threadIdx.x;
    double s = 0.0;
    for (int b = tid; b < BB; b += NTH) {
        int d = d_death[b];           // in [0, TT]
        s += d_S[d];
    }
    red[tid] = s;
    __syncthreads();
    #pragma unroll 1
    for (int off = NTH / 2; off > 0; off >>= 1) {
        if (tid < off) red[tid] += red[tid + off];
        __syncthreads();
    }
    if (tid == 0) out[0] = (float)(red[0] / (double)BB);
}

extern "C" void kernel_launch(void* const* d_in, const int* in_sizes, int n_in,
                              void* d_out, int out_size) {
    const float* acts = (const float*)d_in[0];
    const float* u1   = (const float*)d_in[1];
    const float* u2   = (const float*)d_in[2];
    float* out = (float*)d_out;

    setup_kernel<<<1, NTH>>>(acts);
    dim3 grid(BB / (SCAN_THREADS * 4), (TT + TCHUNK - 1) / TCHUNK);
    scan_kernel<<<grid, SCAN_THREADS>>>(u1, u2);
    finalize_kernel<<<1, NTH>>>(out);
}

// round 4
// speedup vs baseline: 11.0935x; 2.6682x over previous
#include <cuda_runtime.h>
#include <math.h>

#define TT 10000
#define BB 4096
#define BPT 128                         // threads per elementwise block
#define NBLK ((TT + BPT - 1) / BPT)     // 79
#define TCHUNK 8
#define SCAN_THREADS 256

// fp32-rounded constants (match np.float32 of the reference constants)
#define LOG_GAMMA_F  (0.019802627296179712f)
#define ALPHA_F      (-1.0050335853501441e-05f)
#define INIT_LOGW_F  (-1.3943265328171549f)
#define INIT_LOGP_F  (-6.907755278982137f)

// Scratch (device globals — no allocation allowed)
__device__ float  d_thr[TT];
__device__ float  d_filt[TT];
__device__ float  d_c[TT];       // c_t = LOG_GAMMA + log1p(-exp(a_t))
__device__ float  d_f[TT];       // f_t = exp(a_t)
__device__ float  d_lw[TT];      // logw_pre[t]
__device__ double d_csum[NBLK], d_coff[NBLK];
__device__ double d_gsum[NBLK], d_goff[NBLK];
__device__ double d_rsum[NBLK], d_roff[NBLK];
__device__ double d_S[TT + 1];
__device__ int    d_death[BB];
__device__ int    d_Tcut;

// ---- block-local double helpers (BPT = 128 threads, 4 warps) ----
__device__ __forceinline__ double warp_reduce(double v) {
    #pragma unroll
    for (int o = 16; o > 0; o >>= 1) v += __shfl_down_sync(0xffffffffu, v, o);
    return v;
}

__device__ __forceinline__ double block_reduce(double v, double* s4) {
    int lane = threadIdx.x & 31, w = threadIdx.x >> 5;
    double r = warp_reduce(v);
    if (lane == 0) s4[w] = r;
    __syncthreads();
    double tot = s4[0] + s4[1] + s4[2] + s4[3];
    __syncthreads();
    return tot;
}

// exclusive scan over 128 doubles (Hillis-Steele in smem, 7 iters)
__device__ __forceinline__ double block_exscan128(double v, double* sbuf) {
    int tid = threadIdx.x;
    sbuf[tid] = v;
    __syncthreads();
    #pragma unroll
    for (int off = 1; off < BPT; off <<= 1) {
        double x = (tid >= off) ? sbuf[tid - off] : 0.0;
        __syncthreads();
        sbuf[tid] += x;
        __syncthreads();
    }
    double ex = (tid == 0) ? 0.0 : sbuf[tid - 1];
    __syncthreads();
    return ex;
}

// ---------------------------------------------------------------------------
// K1: elementwise c_t, f_t; per-block sums of c. Also resets scratch.
// ---------------------------------------------------------------------------
__global__ void __launch_bounds__(BPT) k1_c(const float* __restrict__ acts) {
    __shared__ double s4[4];
    int t = blockIdx.x * BPT + threadIdx.x;
    if (t < BB) d_death[t] = TT;          // NBLK*BPT = 10112 >= BB
    if (t == 0) d_Tcut = TT;
    double c = 0.0;
    if (t < TT) {
        float f = expf(acts[t]);
        float cf = LOG_GAMMA_F + log1pf(-f);
        d_f[t] = f;
        d_c[t] = cf;
        c = (double)cf;
    }
    double tot = block_reduce(c, s4);
    if (threadIdx.x == 0) d_csum[blockIdx.x] = tot;
}

// ---------------------------------------------------------------------------
// K2: exclusive scan of the NBLK (=79) c block-sums. One tiny block.
// ---------------------------------------------------------------------------
__global__ void __launch_bounds__(BPT) k2_scan_c() {
    __shared__ double sbuf[BPT];
    int i = threadIdx.x;
    double v = (i < NBLK) ? d_csum[i] : 0.0;
    double ex = block_exscan128(v, sbuf);
    if (i < NBLK) d_coff[i] = ex;
}

// ---------------------------------------------------------------------------
// K3: lw[t] = INIT_LOGW + coff[blk] + exscan(c); g_t, rwd_t; block sums.
// ---------------------------------------------------------------------------
__global__ void __launch_bounds__(BPT) k3_lw() {
    __shared__ double sbuf[BPT];
    __shared__ double s4[4];
    int t = blockIdx.x * BPT + threadIdx.x;
    double c = (t < TT) ? (double)d_c[t] : 0.0;
    double ex = block_exscan128(c, sbuf);
    double g = 0.0, r = 0.0;
    if (t < TT) {
        float lw = (float)((double)INIT_LOGW_F + d_coff[blockIdx.x] + ex);
        d_lw[t] = lw;
        g = (double)(ALPHA_F * d_f[t] * expf(lw));       // -> -inf when lw large: ok
        r = (double)expf((lw + d_c[t]) * 0.001f);
    }
    double gt = block_reduce(g, s4);
    double rt = block_reduce(r, s4);
    if (threadIdx.x == 0) { d_gsum[blockIdx.x] = gt; d_rsum[blockIdx.x] = rt; }
}

// ---------------------------------------------------------------------------
// K4: exclusive scans of g and rwd block-sums. One tiny block.
// ---------------------------------------------------------------------------
__global__ void __launch_bounds__(BPT) k4_scan_gr() {
    __shared__ double sbuf[BPT];
    int i = threadIdx.x;
    double v = (i < NBLK) ? d_gsum[i] : 0.0;
    double ex = block_exscan128(v, sbuf);
    if (i < NBLK) d_goff[i] = ex;
    v = (i < NBLK) ? d_rsum[i] : 0.0;
    ex = block_exscan128(v, sbuf);
    if (i < NBLK) d_roff[i] = ex;
}

// ---------------------------------------------------------------------------
// K5: logp -> thr/filt/Tcut; S[t]. Two intra-block exscans.
// ---------------------------------------------------------------------------
__global__ void __launch_bounds__(BPT) k5_final() {
    __shared__ double sbuf[BPT];
    int t = blockIdx.x * BPT + threadIdx.x;
    float lw = 0.f, cf = 0.f;
    double g = 0.0, r = 0.0;
    if (t < TT) {
        lw = d_lw[t];
        cf = d_c[t];
        g = (double)(ALPHA_F * d_f[t] * expf(lw));
        r = (double)expf((lw + cf) * 0.001f);
    }
    double exg = block_exscan128(g, sbuf);
    double exr = block_exscan128(r, sbuf);
    if (t < TT) {
        float logp  = (float)((double)INIT_LOGP_F + d_goff[blockIdx.x] + exg);
        float elp   = expf(logp);
        float logit = logp - log1pf(-elp);
        float thr   = expf(logit) - 1e-12f;
        if (!(thr > 0.0f)) {
            // death impossible: noise <= -log(1e-12) = 27.631
            d_thr[t]  = 0.0f;
            d_filt[t] = 2.0f;     // never passes
            atomicMin(&d_Tcut, t);
        } else {
            d_thr[t] = thr;
            // necessary condition: u2 + eps > exp(-27.631*thr); conservative margins
            d_filt[t] = expf(-27.632f * thr) - 1e-12f - 1e-4f;
        }
        double roff = d_roff[blockIdx.x];
        d_S[t] = roff + exr;
        if (t == TT - 1) d_S[TT] = roff + exr + r;
    }
}

// ---------------------------------------------------------------------------
// Scan: death at (t,b) <=> log(u2+eps) > thr_t * log(u1+eps).
// u2 float4 streaming loads; u2 pre-filter keeps logs + u1 loads to ~3%.
// TCHUNK=8 -> ~560 active blocks for good chip occupancy under T_cut.
// ---------------------------------------------------------------------------
__global__ void __launch_bounds__(SCAN_THREADS) scan_kernel(
        const float* __restrict__ u1, const float* __restrict__ u2) {
    int tcut = d_Tcut;
    int t0   = blockIdx.y * TCHUNK;
    if (t0 >= tcut) return;
    int nt = min(TCHUNK, tcut - t0);

    int b4 = (blockIdx.x * SCAN_THREADS + threadIdx.x) * 4;
    const float4* u2v = (const float4*)u2;

    float4 v[TCHUNK];
    #pragma unroll
    for (int j = 0; j < TCHUNK; j++)
        v[j] = (j < nt) ? __ldcs(&u2v[((size_t)(t0 + j) * BB + b4) >> 2])
                        : make_float4(0.f, 0.f, 0.f, 0.f);

    #pragma unroll
    for (int j = 0; j < TCHUNK; j++) {
        if (j >= nt) break;
        int   tg  = t0 + j;
        float flt = __ldg(&d_filt[tg]);
        float th  = __ldg(&d_thr[tg]);
        float lane[4] = {v[j].x, v[j].y, v[j].z, v[j].w};
        #pragma unroll
        for (int l = 0; l < 4; l++) {
            if (lane[l] > flt) {
                float u1v = __ldcs(&u1[(size_t)tg * BB + b4 + l]);
                float L1  = logf(u1v + 1e-12f);
                float L2  = logf(lane[l] + 1e-12f);
                if (L2 > th * L1) atomicMin(&d_death[b4 + l], tg);
            }
        }
    }
}

// ---------------------------------------------------------------------------
// Finalize: cumrew_b = S[death_b]; mean over batch.
// ---------------------------------------------------------------------------
__global__ void __launch_bounds__(1024) finalize_kernel(float* __restrict__ out) {
    __shared__ double red[1024];
    int tid = threadIdx.x;
    double s = 0.0;
    for (int b = tid; b < BB; b += 1024) s += d_S[d_death[b]];
    red[tid] = s;
    __syncthreads();
    #pragma unroll 1
    for (int off = 512; off > 0; off >>= 1) {
        if (tid < off) red[tid] += red[tid + off];
        __syncthreads();
    }
    if (tid == 0) out[0] = (float)(red[0] / (double)BB);
}

extern "C" void kernel_launch(void* const* d_in, const int* in_sizes, int n_in,
                              void* d_out, int out_size) {
    const float* acts = (const float*)d_in[0];
    const float* u1   = (const float*)d_in[1];
    const float* u2   = (const float*)d_in[2];
    float* out = (float*)d_out;

    k1_c<<<NBLK, BPT>>>(acts);
    k2_scan_c<<<1, BPT>>>();
    k3_lw<<<NBLK, BPT>>>();
    k4_scan_gr<<<1, BPT>>>();
    k5_final<<<NBLK, BPT>>>();
    dim3 grid(BB / (SCAN_THREADS * 4), (TT + TCHUNK - 1) / TCHUNK);
    scan_kernel<<<grid, SCAN_THREADS>>>(u1, u2);
    finalize_kernel<<<1, 1024>>>(out);
}

// round 5
// speedup vs baseline: 11.3278x; 1.0211x over previous
#include <cuda_runtime.h>
#include <math.h>

#define TT 10000
#define BB 4096
#define BPT 128                         // setup threads per block
#define NBLK ((TT + BPT - 1) / BPT)     // 79 setup blocks (all fit in wave 1)
#define TCHUNK 8
#define SCAN_THREADS 256

// fp32-rounded constants (match np.float32 of the reference constants)
#define LOG_GAMMA_F  (0.019802627296179712f)
#define ALPHA_F      (-1.0050335853501441e-05f)
#define INIT_LOGW_F  (-1.3943265328171549f)
#define INIT_LOGP_F  (-6.907755278982137f)

// Scratch (device globals — no allocation allowed).
// Flags/Tcut are zero/TT on the first run via static init; thereafter the
// finalize kernel resets them at the end of each run for the next replay.
__device__ float  d_thr[TT];
__device__ float  d_filt[TT];
__device__ double d_S[TT + 1];
__device__ int    d_death[BB];
__device__ int    d_Tcut = TT;

__device__ double       g_csum[NBLK];
__device__ double       g_gsum[NBLK];
__device__ double       g_rsum[NBLK];
__device__ volatile int g_flag1[NBLK];   // zero-init
__device__ volatile int g_flag2[NBLK];   // zero-init

// ---- block helpers (BPT = 128 threads, 4 warps) ----
__device__ __forceinline__ double warp_reduce(double v) {
    #pragma unroll
    for (int o = 16; o > 0; o >>= 1) v += __shfl_down_sync(0xffffffffu, v, o);
    return v;
}

__device__ __forceinline__ double block_reduce(double v, double* s4) {
    int lane = threadIdx.x & 31, w = threadIdx.x >> 5;
    double r = warp_reduce(v);
    __syncthreads();                // protect s4 reuse across calls
    if (lane == 0) s4[w] = r;
    __syncthreads();
    double tot = s4[0] + s4[1] + s4[2] + s4[3];
    return tot;
}

// exclusive scan over BPT doubles; also returns the block total
__device__ __forceinline__ double block_exscan(double v, double* sbuf, double* tot) {
    int tid = threadIdx.x;
    __syncthreads();                // protect sbuf reuse across calls
    sbuf[tid] = v;
    __syncthreads();
    #pragma unroll
    for (int off = 1; off < BPT; off <<= 1) {
        double x = (tid >= off) ? sbuf[tid - off] : 0.0;
        __syncthreads();
        sbuf[tid] += x;
        __syncthreads();
    }
    double ex = (tid == 0) ? 0.0 : sbuf[tid - 1];
    *tot = sbuf[BPT - 1];
    return ex;
}

// ---------------------------------------------------------------------------
// Setup: ONE kernel, 79 blocks, decoupled lookback (2 channels).
//   c_t = LOG_GAMMA + log1p(-exp(a_t));  lw_t = INIT_LOGW + prefix(c)
//   g_t = ALPHA * f_t * exp(lw_t);       logp_t = INIT_LOGP + prefix(g)
//   r_t = exp((lw_t + c_t)/1000);        S[k]   = prefix(r)
//   thr_t = exp(logit_t) - eps; filt_t = conservative u2 lower bound; Tcut.
// All 79 blocks are co-resident (<=148 SMs) so flag spins cannot deadlock.
// ---------------------------------------------------------------------------
__global__ void __launch_bounds__(BPT) setup_kernel(const float* __restrict__ acts) {
    __shared__ double sbuf[BPT];
    __shared__ double s4[4];
    int tid = threadIdx.x;
    int bid = blockIdx.x;
    int t = bid * BPT + tid;

    if (t < BB) d_death[t] = TT;      // blocks 0..31 cover the batch

    float f = 0.f, c = 0.f;
    if (t < TT) {
        f = expf(acts[t]);
        c = LOG_GAMMA_F + log1pf(-f);
    }

    // ---- channel 1: prefix of c across blocks ----
    double ctot;
    double exc = block_exscan((double)c, sbuf, &ctot);
    if (tid == 0) {
        g_csum[bid] = ctot;
        __threadfence();
        g_flag1[bid] = 1;
    }
    double part = 0.0;
    if (tid < bid) {                  // bid <= 78 < 128 threads
        while (g_flag1[tid] == 0) __nanosleep(32);
        __threadfence();
        part = g_csum[tid];
    }
    double coff = block_reduce(part, s4);

    // ---- per-element lw, g, r ----
    float lw = 0.f;
    double g = 0.0, r = 0.0;
    if (t < TT) {
        lw = (float)((double)INIT_LOGW_F + coff + exc);
        g = (double)(ALPHA_F * f * expf(lw));       // -> -inf for large lw: ok
        r = (double)expf((lw + c) * 0.001f);
    }

    // ---- channel 2: prefixes of g and r across blocks ----
    double gtot, rtot;
    double exg = block_exscan(g, sbuf, &gtot);
    double exr = block_exscan(r, sbuf, &rtot);
    if (tid == 0) {
        g_gsum[bid] = gtot;
        g_rsum[bid] = rtot;
        __threadfence();
        g_flag2[bid] = 1;
    }
    double gpart = 0.0, rpart = 0.0;
    if (tid < bid) {
        while (g_flag2[tid] == 0) __nanosleep(32);
        __threadfence();
        gpart = g_gsum[tid];
        rpart = g_rsum[tid];
    }
    double goff = block_reduce(gpart, s4);
    double roff = block_reduce(rpart, s4);

    // ---- elementwise outputs ----
    if (t < TT) {
        float logp  = (float)((double)INIT_LOGP_F + goff + exg);
        float elp   = expf(logp);
        float logit = logp - log1pf(-elp);
        float thr   = expf(logit) - 1e-12f;
        if (!(thr > 0.0f)) {
            // death impossible at/after here: noise <= -log(1e-12) = 27.631
            d_thr[t]  = 0.0f;
            d_filt[t] = 2.0f;       // never passes
            atomicMin(&d_Tcut, t);
        } else {
            d_thr[t] = thr;
            // necessary condition: u2 + eps > exp(-27.631*thr); conservative margins
            d_filt[t] = expf(-27.632f * thr) - 1e-12f - 1e-4f;
        }
        d_S[t] = roff + exr;
        if (t == TT - 1) d_S[TT] = roff + exr + r;
    }
}

// ---------------------------------------------------------------------------
// Scan: death at (t,b) <=> log(u2+eps) > thr_t * log(u1+eps).
// float4 u2 streaming loads; u2 pre-filter keeps logs + u1 loads to ~3%.
// ---------------------------------------------------------------------------
__global__ void __launch_bounds__(SCAN_THREADS) scan_kernel(
        const float* __restrict__ u1, const float* __restrict__ u2) {
    int tcut = d_Tcut;
    int t0   = blockIdx.y * TCHUNK;
    if (t0 >= tcut) return;
    int nt = min(TCHUNK, tcut - t0);

    int b4 = (blockIdx.x * SCAN_THREADS + threadIdx.x) * 4;
    const float4* u2v = (const float4*)u2;

    float4 v[TCHUNK];
    #pragma unroll
    for (int j = 0; j < TCHUNK; j++)
        v[j] = (j < nt) ? __ldcs(&u2v[((size_t)(t0 + j) * BB + b4) >> 2])
                        : make_float4(0.f, 0.f, 0.f, 0.f);

    #pragma unroll
    for (int j = 0; j < TCHUNK; j++) {
        if (j >= nt) break;
        int   tg  = t0 + j;
        float flt = __ldg(&d_filt[tg]);
        float th  = __ldg(&d_thr[tg]);
        float lane[4] = {v[j].x, v[j].y, v[j].z, v[j].w};
        #pragma unroll
        for (int l = 0; l < 4; l++) {
            if (lane[l] > flt) {
                float u1v = __ldcs(&u1[(size_t)tg * BB + b4 + l]);
                float L1  = logf(u1v + 1e-12f);
                float L2  = logf(lane[l] + 1e-12f);
                if (L2 > th * L1) atomicMin(&d_death[b4 + l], tg);
            }
        }
    }
}

// ---------------------------------------------------------------------------
// Finalize: cumrew_b = S[death_b]; mean. Also resets lookback flags + Tcut
// for the next graph replay (runs strictly after all their uses this run).
// ---------------------------------------------------------------------------
__global__ void __launch_bounds__(1024) finalize_kernel(float* __restrict__ out) {
    __shared__ double red[1024];
    int tid = threadIdx.x;
    double s = 0.0;
    for (int b = tid; b < BB; b += 1024) s += d_S[d_death[b]];
    red[tid] = s;
    __syncthreads();
    #pragma unroll 1
    for (int off = 512; off > 0; off >>= 1) {
        if (tid < off) red[tid] += red[tid + off];
        __syncthreads();
    }
    if (tid == 0) out[0] = (float)(red[0] / (double)BB);

    // resets for next replay
    if (tid < NBLK) { g_flag1[tid] = 0; g_flag2[tid] = 0; }
    if (tid == 0) d_Tcut = TT;
}

extern "C" void kernel_launch(void* const* d_in, const int* in_sizes, int n_in,
                              void* d_out, int out_size) {
    const float* acts = (const float*)d_in[0];
    const float* u1   = (const float*)d_in[1];
    const float* u2   = (const float*)d_in[2];
    float* out = (float*)d_out;

    setup_kernel<<<NBLK, BPT>>>(acts);
    dim3 grid(BB / (SCAN_THREADS * 4), (TT + TCHUNK - 1) / TCHUNK);
    scan_kernel<<<grid, SCAN_THREADS>>>(u1, u2);
    finalize_kernel<<<1, 1024>>>(out);
}